// round 3
// baseline (speedup 1.0000x reference)
#include <cuda_runtime.h>
#include <math.h>
#include <stdint.h>

// Problem dims
// B=8, T=1024, E=1024, H=16, HD=64, FF=4096, M = B*T = 8192

// ---------------- scratch (device globals; no allocations allowed) ----------
__device__ float g_qkv[(size_t)8192 * 3072];
__device__ float g_attn[(size_t)8192 * 1024];
__device__ float g_s[(size_t)8192 * 1024];
__device__ float g_x1[(size_t)8192 * 1024];
__device__ float g_ff[(size_t)8192 * 4096];
__device__ int   g_len[8];

// ---------------- padding-mask dtype detection + length extraction ----------
// The reference's self_padding_mask is a numpy bool [8,1024]; the harness may
// deliver it as uint8, int32, or float32. Detect from content (the mask is a
// monotone tail of 1s per row), then write per-batch first-padded-index.
// Scanning 2048 words is safe for every layout (== whole buffer if uint8).
__global__ void mask_len_kernel(const void* mask) {
    __shared__ int sGT1, sEQ1, sF32;
    if (threadIdx.x == 0) { sGT1 = 0; sEQ1 = 0; sF32 = 0; }
    __syncthreads();
    const unsigned int* w = (const unsigned int*)mask;
    int gt1 = 0, eq1 = 0, f32 = 0;
    for (int i = threadIdx.x; i < 2048; i += 256) {
        unsigned int v = w[i];
        if (v == 0x3F800000u)      f32 = 1;
        else if (v == 1u)          eq1 = 1;
        else if (v != 0u)          gt1 = 1;
    }
    if (f32) atomicOr(&sF32, 1);
    if (gt1) atomicOr(&sGT1, 1);
    if (eq1) atomicOr(&sEQ1, 1);
    __syncthreads();
    if (threadIdx.x < 8) {
        const int b = threadIdx.x;
        int len = 1024;
        if (sF32) {                    // float32 bool
            const float* p = (const float*)mask;
            for (int k = 0; k < 1024; ++k)
                if (p[(size_t)b * 1024 + k] != 0.f) { len = k; break; }
        } else if (sGT1) {             // uint8 bool
            const unsigned char* p = (const unsigned char*)mask;
            for (int k = 0; k < 1024; ++k)
                if (p[(size_t)b * 1024 + k]) { len = k; break; }
        } else if (sEQ1) {             // int32 bool
            const int* p = (const int*)mask;
            for (int k = 0; k < 1024; ++k)
                if (p[(size_t)b * 1024 + k]) { len = k; break; }
        }                              // else: all zero -> no padding
        g_len[b] = len;
    }
}

// ---------------- fp32 SGEMM: C[M,N] = A[M,K] @ W[N,K]^T + bias (+res/relu) --
// 128x128 tile, K-step 8, 256 threads, 8x8 per-thread microtile.
// EPI: 0 = +bias, 1 = +bias+residual, 2 = +bias+relu
template <int EPI>
__global__ __launch_bounds__(256) void sgemm_kernel(
    const float* __restrict__ A, const float* __restrict__ W,
    const float* __restrict__ bias, const float* __restrict__ R,
    float* __restrict__ C, int Ksz, int Nsz)
{
    __shared__ float As[8][128];
    __shared__ float Bs[8][128];

    const int tid  = threadIdx.x;
    const int m0   = blockIdx.y * 128;
    const int n0   = blockIdx.x * 128;
    const int lrow = tid >> 1;          // 0..127
    const int lcol = (tid & 1) * 4;     // 0 or 4
    const int ty   = tid >> 4;          // 0..15
    const int tx   = tid & 15;          // 0..15

    float acc[8][8];
#pragma unroll
    for (int i = 0; i < 8; ++i)
#pragma unroll
        for (int j = 0; j < 8; ++j) acc[i][j] = 0.f;

    const float* Ap = A + (size_t)(m0 + lrow) * Ksz + lcol;
    const float* Wp = W + (size_t)(n0 + lrow) * Ksz + lcol;

    for (int k0 = 0; k0 < Ksz; k0 += 8) {
        float4 a = *(const float4*)(Ap + k0);
        float4 b = *(const float4*)(Wp + k0);
        As[lcol + 0][lrow] = a.x; As[lcol + 1][lrow] = a.y;
        As[lcol + 2][lrow] = a.z; As[lcol + 3][lrow] = a.w;
        Bs[lcol + 0][lrow] = b.x; Bs[lcol + 1][lrow] = b.y;
        Bs[lcol + 2][lrow] = b.z; Bs[lcol + 3][lrow] = b.w;
        __syncthreads();

#pragma unroll
        for (int kk = 0; kk < 8; ++kk) {
            float av[8], bv[8];
            *(float4*)&av[0] = *(const float4*)&As[kk][ty * 8];
            *(float4*)&av[4] = *(const float4*)&As[kk][ty * 8 + 4];
            *(float4*)&bv[0] = *(const float4*)&Bs[kk][tx * 8];
            *(float4*)&bv[4] = *(const float4*)&Bs[kk][tx * 8 + 4];
#pragma unroll
            for (int i = 0; i < 8; ++i)
#pragma unroll
                for (int j = 0; j < 8; ++j)
                    acc[i][j] = fmaf(av[i], bv[j], acc[i][j]);
        }
        __syncthreads();
    }

    const int mr = m0 + ty * 8;
    const int nc = n0 + tx * 8;
#pragma unroll
    for (int i = 0; i < 8; ++i) {
        size_t rb = (size_t)(mr + i) * Nsz + nc;
#pragma unroll
        for (int j = 0; j < 8; ++j) {
            float v = acc[i][j] + bias[nc + j];
            if (EPI == 1) v += R[rb + j];
            if (EPI == 2) v = fmaxf(v, 0.f);
            C[rb + j] = v;
        }
    }
}

// ---------------- attention: flash-style, per (b, h, 64-query tile) --------
// qkv layout: [B*T, 3072], Q at col h*64, K at 1024+h*64, V at 2048+h*64.
// Causal mask from indices; padding mask via per-batch length (g_len).
__global__ __launch_bounds__(256) void attn_kernel(
    const float* __restrict__ qkv, const int* __restrict__ lenv,
    float* __restrict__ out)
{
    __shared__ float Qs[64 * 64];
    __shared__ float KPs[64 * 64];   // K tile (swizzled), then reused for P
    __shared__ float Vs[64 * 64];

    const int tid = threadIdx.x;
    const int tx  = tid & 15;       // 4 key-cols / out-dims
    const int ty  = tid >> 4;       // 4 query rows
    const int b   = blockIdx.z;
    const int h   = blockIdx.y;
    const int qt  = blockIdx.x;
    const int q0  = qt * 64;
    const int blen = lenv[b];
    const float scale = 0.125f;     // HD^-0.5

    // load Q tile, pre-scaled
    for (int i = tid; i < 64 * 16; i += 256) {
        int r = i >> 4, c4 = (i & 15) << 2;
        float4 v = *(const float4*)&qkv[(size_t)(b * 1024 + q0 + r) * 3072 + h * 64 + c4];
        float* q = &Qs[r * 64 + c4];
        q[0] = v.x * scale; q[1] = v.y * scale; q[2] = v.z * scale; q[3] = v.w * scale;
    }

    float O[4][4];
    float m_i[4], l_i[4];
#pragma unroll
    for (int i = 0; i < 4; ++i) {
        m_i[i] = -1e30f; l_i[i] = 0.f;
#pragma unroll
        for (int j = 0; j < 4; ++j) O[i][j] = 0.f;
    }

    for (int kt = 0; kt <= qt; ++kt) {
        const int k0 = kt * 64;
        __syncthreads();   // prior-iteration P/V readers done (also fences Q stores)

        // load K (XOR-swizzled chunks) and V tiles
        for (int i = tid; i < 64 * 16; i += 256) {
            int r = i >> 4, c4 = (i & 15);
            size_t base = (size_t)(b * 1024 + k0 + r) * 3072 + h * 64 + (c4 << 2);
            float4 kv = *(const float4*)&qkv[base + 1024];
            float4 vv = *(const float4*)&qkv[base + 2048];
            *(float4*)&KPs[r * 64 + ((c4 ^ (r >> 2)) << 2)] = kv;
            *(float4*)&Vs[r * 64 + (c4 << 2)] = vv;
        }
        __syncthreads();

        // S = Q @ K^T  (4x4 per thread)
        float s[4][4];
#pragma unroll
        for (int i = 0; i < 4; ++i)
#pragma unroll
            for (int j = 0; j < 4; ++j) s[i][j] = 0.f;

        const float* qp[4];
        const float* kp[4];
        int sw[4];
#pragma unroll
        for (int i = 0; i < 4; ++i) qp[i] = &Qs[(ty * 4 + i) * 64];
#pragma unroll
        for (int j = 0; j < 4; ++j) {
            int key = tx * 4 + j;
            kp[j] = &KPs[key * 64];
            sw[j] = key >> 2;
        }

#pragma unroll
        for (int d4 = 0; d4 < 16; ++d4) {
            float4 qa[4];
#pragma unroll
            for (int i = 0; i < 4; ++i) qa[i] = *(const float4*)(qp[i] + (d4 << 2));
#pragma unroll
            for (int j = 0; j < 4; ++j) {
                float4 kb = *(const float4*)(kp[j] + ((d4 ^ sw[j]) << 2));
#pragma unroll
                for (int i = 0; i < 4; ++i)
                    s[i][j] += qa[i].x * kb.x + qa[i].y * kb.y + qa[i].z * kb.z + qa[i].w * kb.w;
            }
        }

        // mask: causal (k > q) OR key padded (k >= length[b])
#pragma unroll
        for (int j = 0; j < 4; ++j) {
            int gk = k0 + tx * 4 + j;
            bool pd = gk >= blen;
#pragma unroll
            for (int i = 0; i < 4; ++i) {
                int gq = q0 + ty * 4 + i;
                if (pd || gk > gq) s[i][j] = -1e30f;
            }
        }

        // online softmax update (row reduce over the 16 tx lanes)
#pragma unroll
        for (int i = 0; i < 4; ++i) {
            float mx = fmaxf(fmaxf(s[i][0], s[i][1]), fmaxf(s[i][2], s[i][3]));
#pragma unroll
            for (int off = 8; off; off >>= 1)
                mx = fmaxf(mx, __shfl_xor_sync(0xffffffffu, mx, off));
            float mnew  = fmaxf(m_i[i], mx);
            float alpha = __expf(m_i[i] - mnew);
            float sum = 0.f;
#pragma unroll
            for (int j = 0; j < 4; ++j) {
                float p = __expf(s[i][j] - mnew);
                s[i][j] = p;
                sum += p;
            }
#pragma unroll
            for (int off = 8; off; off >>= 1)
                sum += __shfl_xor_sync(0xffffffffu, sum, off);
            l_i[i] = l_i[i] * alpha + sum;
            m_i[i] = mnew;
#pragma unroll
            for (int j = 0; j < 4; ++j) O[i][j] *= alpha;
        }

        __syncthreads();   // everyone done reading K
        // store P (plain layout)
#pragma unroll
        for (int i = 0; i < 4; ++i)
#pragma unroll
            for (int j = 0; j < 4; ++j)
                KPs[(ty * 4 + i) * 64 + tx * 4 + j] = s[i][j];
        __syncthreads();

        // O += P @ V
#pragma unroll
        for (int k4 = 0; k4 < 16; ++k4) {
            float p[4][4];
#pragma unroll
            for (int i = 0; i < 4; ++i)
                *(float4*)&p[i][0] = *(const float4*)&KPs[(ty * 4 + i) * 64 + (k4 << 2)];
            float vr[4][4];
#pragma unroll
            for (int kk = 0; kk < 4; ++kk)
                *(float4*)&vr[kk][0] = *(const float4*)&Vs[(k4 * 4 + kk) * 64 + tx * 4];
#pragma unroll
            for (int i = 0; i < 4; ++i)
#pragma unroll
                for (int j = 0; j < 4; ++j)
                    O[i][j] += p[i][0] * vr[0][j] + p[i][1] * vr[1][j]
                             + p[i][2] * vr[2][j] + p[i][3] * vr[3][j];
        }
    }

    // epilogue: divide by row sums, write [B*T, E]
#pragma unroll
    for (int i = 0; i < 4; ++i) {
        float inv = 1.f / l_i[i];
#pragma unroll
        for (int j = 0; j < 4; ++j)
            out[(size_t)(b * 1024 + q0 + ty * 4 + i) * 1024 + h * 64 + tx * 4 + j] = O[i][j] * inv;
    }
}

// ---------------- LayerNorm: one row (1024) per block, 256 threads ---------
__global__ __launch_bounds__(256) void ln_kernel(
    const float* __restrict__ X, const float* __restrict__ w,
    const float* __restrict__ bb, float* __restrict__ Y)
{
    const int row = blockIdx.x;
    const int t   = threadIdx.x;
    float4 x = *(const float4*)&X[(size_t)row * 1024 + t * 4];
    float s = x.x + x.y + x.z + x.w;
    float q = fmaf(x.x, x.x, fmaf(x.y, x.y, fmaf(x.z, x.z, x.w * x.w)));
#pragma unroll
    for (int off = 16; off; off >>= 1) {
        s += __shfl_xor_sync(0xffffffffu, s, off);
        q += __shfl_xor_sync(0xffffffffu, q, off);
    }
    __shared__ float ss[8], qq[8];
    const int warp = t >> 5, lane = t & 31;
    if (lane == 0) { ss[warp] = s; qq[warp] = q; }
    __syncthreads();
    float S = 0.f, Q2 = 0.f;
#pragma unroll
    for (int i = 0; i < 8; ++i) { S += ss[i]; Q2 += qq[i]; }
    const float mean = S * (1.0f / 1024.0f);
    const float var  = fmaxf(Q2 * (1.0f / 1024.0f) - mean * mean, 0.f);
    const float inv  = rsqrtf(var + 1e-12f);
    float4 wv = *(const float4*)&w[t * 4];
    float4 bv = *(const float4*)&bb[t * 4];
    float4 y;
    y.x = wv.x * (x.x - mean) * inv + bv.x;
    y.y = wv.y * (x.y - mean) * inv + bv.y;
    y.z = wv.z * (x.z - mean) * inv + bv.z;
    y.w = wv.w * (x.w - mean) * inv + bv.w;
    *(float4*)&Y[(size_t)row * 1024 + t * 4] = y;
}

// ---------------- launch ----------------------------------------------------
extern "C" void kernel_launch(void* const* d_in, const int* in_sizes, int n_in,
                              void* d_out, int out_size)
{
    const float* x     = (const float*)d_in[0];
    const float* in_w  = (const float*)d_in[1];
    const float* in_b  = (const float*)d_in[2];
    const float* out_w = (const float*)d_in[3];
    const float* out_b = (const float*)d_in[4];
    const float* fc1_w = (const float*)d_in[5];
    const float* fc1_b = (const float*)d_in[6];
    const float* fc2_w = (const float*)d_in[7];
    const float* fc2_b = (const float*)d_in[8];
    const float* ln1_w = (const float*)d_in[9];
    const float* ln1_b = (const float*)d_in[10];
    const float* ln2_w = (const float*)d_in[11];
    const float* ln2_b = (const float*)d_in[12];
    const void*  pad   = d_in[13];
    // d_in[14] = attn_mask (causal triu) — recomputed from indices in-kernel
    float* out = (float*)d_out;

    float *qkv, *attn, *sbuf, *x1, *ff;
    int* lenv;
    cudaGetSymbolAddress((void**)&qkv,  g_qkv);
    cudaGetSymbolAddress((void**)&attn, g_attn);
    cudaGetSymbolAddress((void**)&sbuf, g_s);
    cudaGetSymbolAddress((void**)&x1,   g_x1);
    cudaGetSymbolAddress((void**)&ff,   g_ff);
    cudaGetSymbolAddress((void**)&lenv, g_len);

    // 0) decode padding mask dtype + per-batch lengths
    mask_len_kernel<<<1, 256>>>(pad);
    // 1) qkv = x @ in_w^T + in_b           [8192, 3072]
    sgemm_kernel<0><<<dim3(3072 / 128, 8192 / 128), 256>>>(x, in_w, in_b, nullptr, qkv, 1024, 3072);
    // 2) attention -> attn                 [8192, 1024]
    attn_kernel<<<dim3(16, 16, 8), 256>>>(qkv, lenv, attn);
    // 3) s1 = attn @ out_w^T + out_b + x   [8192, 1024]
    sgemm_kernel<1><<<dim3(1024 / 128, 8192 / 128), 256>>>(attn, out_w, out_b, x, sbuf, 1024, 1024);
    // 4) x1 = LN1(s1)
    ln_kernel<<<8192, 256>>>(sbuf, ln1_w, ln1_b, x1);
    // 5) ff = relu(x1 @ fc1_w^T + fc1_b)   [8192, 4096]
    sgemm_kernel<2><<<dim3(4096 / 128, 8192 / 128), 256>>>(x1, fc1_w, fc1_b, nullptr, ff, 1024, 4096);
    // 6) s2 = ff @ fc2_w^T + fc2_b + x1    [8192, 1024]
    sgemm_kernel<1><<<dim3(1024 / 128, 8192 / 128), 256>>>(ff, fc2_w, fc2_b, x1, sbuf, 4096, 1024);
    // 7) out = LN2(s2)
    ln_kernel<<<8192, 256>>>(sbuf, ln2_w, ln2_b, out);
}

// round 4
// speedup vs baseline: 2.3190x; 2.3190x over previous
#include <cuda_runtime.h>
#include <math.h>
#include <stdint.h>

// Problem dims: B=8, T=1024, E=1024, H=16, HD=64, FF=4096, M = B*T = 8192

// ---------------- scratch (device globals; no allocations allowed) ----------
__device__ float g_qkv[(size_t)8192 * 3072];
__device__ float g_attn[(size_t)8192 * 1024];
__device__ float g_s[(size_t)8192 * 1024];
__device__ float g_x1[(size_t)8192 * 1024];
__device__ float g_ff[(size_t)8192 * 4096];
__device__ int   g_len[8];

// ---------------- padding-mask dtype detection + length extraction ----------
__global__ void mask_len_kernel(const void* mask) {
    __shared__ int sGT1, sEQ1, sF32;
    if (threadIdx.x == 0) { sGT1 = 0; sEQ1 = 0; sF32 = 0; }
    __syncthreads();
    const unsigned int* w = (const unsigned int*)mask;
    int gt1 = 0, eq1 = 0, f32 = 0;
    for (int i = threadIdx.x; i < 2048; i += 256) {
        unsigned int v = w[i];
        if (v == 0x3F800000u)      f32 = 1;
        else if (v == 1u)          eq1 = 1;
        else if (v != 0u)          gt1 = 1;
    }
    if (f32) atomicOr(&sF32, 1);
    if (gt1) atomicOr(&sGT1, 1);
    if (eq1) atomicOr(&sEQ1, 1);
    __syncthreads();
    if (threadIdx.x < 8) {
        const int b = threadIdx.x;
        int len = 1024;
        if (sF32) {
            const float* p = (const float*)mask;
            for (int k = 0; k < 1024; ++k)
                if (p[(size_t)b * 1024 + k] != 0.f) { len = k; break; }
        } else if (sGT1) {
            const unsigned char* p = (const unsigned char*)mask;
            for (int k = 0; k < 1024; ++k)
                if (p[(size_t)b * 1024 + k]) { len = k; break; }
        } else if (sEQ1) {
            const int* p = (const int*)mask;
            for (int k = 0; k < 1024; ++k)
                if (p[(size_t)b * 1024 + k]) { len = k; break; }
        }
        g_len[b] = len;
    }
}

// ---------------- tf32 tensor-core GEMM ------------------------------------
// C[M,N] = A[M,K] @ W[N,K]^T + bias (+res / +relu), fp32 accumulate.
// 128x128 block tile, kstep=16, 256 threads = 8 warps (4m x 2n),
// warp tile 32x64 via m16n8k8 tf32 mma (2 m-atoms x 8 n-atoms).
// SMEM layout [m][k] with 20-word row stride: fragment loads are
// conflict-free (bank = (20m + k) mod 32 all-distinct), stores are STS.128.

__device__ __forceinline__ uint32_t f2tf(float x) {
    uint32_t r;
    asm("cvt.rna.tf32.f32 %0, %1;" : "=r"(r) : "f"(x));
    return r;
}

__device__ __forceinline__ void mma_tf32(float* d, const uint32_t* a, const uint32_t* b) {
    asm volatile(
        "mma.sync.aligned.m16n8k8.row.col.f32.tf32.tf32.f32 "
        "{%0,%1,%2,%3}, {%4,%5,%6,%7}, {%8,%9}, {%0,%1,%2,%3};"
        : "+f"(d[0]), "+f"(d[1]), "+f"(d[2]), "+f"(d[3])
        : "r"(a[0]), "r"(a[1]), "r"(a[2]), "r"(a[3]), "r"(b[0]), "r"(b[1]));
}

template <int EPI>  // 0: +bias, 1: +bias+residual, 2: +bias+relu
__global__ __launch_bounds__(256, 2) void tgemm_kernel(
    const float* __restrict__ A, const float* __restrict__ W,
    const float* __restrict__ bias, const float* __restrict__ R,
    float* __restrict__ C, int Ksz, int Nsz)
{
    __shared__ uint32_t As[128][20];   // [m][k], stride 20 words
    __shared__ uint32_t Bs[128][20];   // [n][k]

    const int tid  = threadIdx.x;
    const int lane = tid & 31;
    const int warp = tid >> 5;
    const int wm   = warp & 3;        // 0..3 (m)
    const int wn   = warp >> 2;       // 0..1 (n)
    const int m0   = blockIdx.y * 128;
    const int n0   = blockIdx.x * 128;

    // global staging map: thread loads rows lr and lr+64, cols lc..lc+3
    const int lr = tid >> 2;          // 0..63
    const int lc = (tid & 3) * 4;     // 0,4,8,12

    const float* Ap0 = A + (size_t)(m0 + lr) * Ksz + lc;
    const float* Ap1 = A + (size_t)(m0 + lr + 64) * Ksz + lc;
    const float* Wp0 = W + (size_t)(n0 + lr) * Ksz + lc;
    const float* Wp1 = W + (size_t)(n0 + lr + 64) * Ksz + lc;

    float acc[2][8][4];
#pragma unroll
    for (int i = 0; i < 2; ++i)
#pragma unroll
        for (int j = 0; j < 8; ++j)
#pragma unroll
            for (int r = 0; r < 4; ++r) acc[i][j][r] = 0.f;

    float4 pa0 = *(const float4*)Ap0;
    float4 pa1 = *(const float4*)Ap1;
    float4 pb0 = *(const float4*)Wp0;
    float4 pb1 = *(const float4*)Wp1;

    const int mrow = wm * 32 + (lane >> 2);   // a-frag base row
    const int ncol = wn * 64 + (lane >> 2);   // b-frag base col
    const int kq   = lane & 3;                // k within quad

    for (int k0 = 0; k0 < Ksz; k0 += 16) {
        // stage (convert to tf32), STS.128 per quad
        {
            uint32_t t0[4] = { f2tf(pa0.x), f2tf(pa0.y), f2tf(pa0.z), f2tf(pa0.w) };
            *(uint4*)&As[lr][lc] = *(uint4*)t0;
            uint32_t t1[4] = { f2tf(pa1.x), f2tf(pa1.y), f2tf(pa1.z), f2tf(pa1.w) };
            *(uint4*)&As[lr + 64][lc] = *(uint4*)t1;
            uint32_t t2[4] = { f2tf(pb0.x), f2tf(pb0.y), f2tf(pb0.z), f2tf(pb0.w) };
            *(uint4*)&Bs[lr][lc] = *(uint4*)t2;
            uint32_t t3[4] = { f2tf(pb1.x), f2tf(pb1.y), f2tf(pb1.z), f2tf(pb1.w) };
            *(uint4*)&Bs[lr + 64][lc] = *(uint4*)t3;
        }
        __syncthreads();

        if (k0 + 16 < Ksz) {  // prefetch next tile
            pa0 = *(const float4*)(Ap0 + k0 + 16);
            pa1 = *(const float4*)(Ap1 + k0 + 16);
            pb0 = *(const float4*)(Wp0 + k0 + 16);
            pb1 = *(const float4*)(Wp1 + k0 + 16);
        }

#pragma unroll
        for (int kk = 0; kk < 16; kk += 8) {
            uint32_t af[2][4];
#pragma unroll
            for (int i = 0; i < 2; ++i) {
                int r = mrow + i * 16;
                af[i][0] = As[r     ][kk + kq];
                af[i][1] = As[r +  8][kk + kq];
                af[i][2] = As[r     ][kk + 4 + kq];
                af[i][3] = As[r +  8][kk + 4 + kq];
            }
#pragma unroll
            for (int j = 0; j < 8; ++j) {
                uint32_t bf[2];
                int c = ncol + j * 8;
                bf[0] = Bs[c][kk + kq];
                bf[1] = Bs[c][kk + 4 + kq];
                mma_tf32(acc[0][j], af[0], bf);
                mma_tf32(acc[1][j], af[1], bf);
            }
        }
        __syncthreads();
    }

    // epilogue: c0,c1 -> (row, col..col+1); c2,c3 -> (row+8, ...)
#pragma unroll
    for (int i = 0; i < 2; ++i) {
        int row = m0 + wm * 32 + i * 16 + (lane >> 2);
#pragma unroll
        for (int j = 0; j < 8; ++j) {
            int col = n0 + wn * 64 + j * 8 + (lane & 3) * 2;
            float b0v = bias[col], b1v = bias[col + 1];
            size_t o0 = (size_t)row * Nsz + col;
            size_t o1 = (size_t)(row + 8) * Nsz + col;
            float v0 = acc[i][j][0] + b0v, v1 = acc[i][j][1] + b1v;
            float v2 = acc[i][j][2] + b0v, v3 = acc[i][j][3] + b1v;
            if (EPI == 1) {
                v0 += R[o0]; v1 += R[o0 + 1];
                v2 += R[o1]; v3 += R[o1 + 1];
            }
            if (EPI == 2) {
                v0 = fmaxf(v0, 0.f); v1 = fmaxf(v1, 0.f);
                v2 = fmaxf(v2, 0.f); v3 = fmaxf(v3, 0.f);
            }
            float2 w0 = { v0, v1 }, w1 = { v2, v3 };
            *(float2*)&C[o0] = w0;
            *(float2*)&C[o1] = w1;
        }
    }
}

// ---------------- attention: flash-style, per (b, h, 64-query tile) --------
__global__ __launch_bounds__(256) void attn_kernel(
    const float* __restrict__ qkv, const int* __restrict__ lenv,
    float* __restrict__ out)
{
    __shared__ float Qs[64 * 64];
    __shared__ float KPs[64 * 64];
    __shared__ float Vs[64 * 64];

    const int tid = threadIdx.x;
    const int tx  = tid & 15;
    const int ty  = tid >> 4;
    const int b   = blockIdx.z;
    const int h   = blockIdx.y;
    const int qt  = blockIdx.x;
    const int q0  = qt * 64;
    const int blen = lenv[b];
    const float scale = 0.125f;

    for (int i = tid; i < 64 * 16; i += 256) {
        int r = i >> 4, c4 = (i & 15) << 2;
        float4 v = *(const float4*)&qkv[(size_t)(b * 1024 + q0 + r) * 3072 + h * 64 + c4];
        float* q = &Qs[r * 64 + c4];
        q[0] = v.x * scale; q[1] = v.y * scale; q[2] = v.z * scale; q[3] = v.w * scale;
    }

    float O[4][4];
    float m_i[4], l_i[4];
#pragma unroll
    for (int i = 0; i < 4; ++i) {
        m_i[i] = -1e30f; l_i[i] = 0.f;
#pragma unroll
        for (int j = 0; j < 4; ++j) O[i][j] = 0.f;
    }

    for (int kt = 0; kt <= qt; ++kt) {
        const int k0 = kt * 64;
        __syncthreads();

        for (int i = tid; i < 64 * 16; i += 256) {
            int r = i >> 4, c4 = (i & 15);
            size_t base = (size_t)(b * 1024 + k0 + r) * 3072 + h * 64 + (c4 << 2);
            float4 kv = *(const float4*)&qkv[base + 1024];
            float4 vv = *(const float4*)&qkv[base + 2048];
            *(float4*)&KPs[r * 64 + ((c4 ^ (r >> 2)) << 2)] = kv;
            *(float4*)&Vs[r * 64 + (c4 << 2)] = vv;
        }
        __syncthreads();

        float s[4][4];
#pragma unroll
        for (int i = 0; i < 4; ++i)
#pragma unroll
            for (int j = 0; j < 4; ++j) s[i][j] = 0.f;

        const float* qp[4];
        const float* kp[4];
        int sw[4];
#pragma unroll
        for (int i = 0; i < 4; ++i) qp[i] = &Qs[(ty * 4 + i) * 64];
#pragma unroll
        for (int j = 0; j < 4; ++j) {
            int key = tx * 4 + j;
            kp[j] = &KPs[key * 64];
            sw[j] = key >> 2;
        }

#pragma unroll
        for (int d4 = 0; d4 < 16; ++d4) {
            float4 qa[4];
#pragma unroll
            for (int i = 0; i < 4; ++i) qa[i] = *(const float4*)(qp[i] + (d4 << 2));
#pragma unroll
            for (int j = 0; j < 4; ++j) {
                float4 kb = *(const float4*)(kp[j] + ((d4 ^ sw[j]) << 2));
#pragma unroll
                for (int i = 0; i < 4; ++i)
                    s[i][j] += qa[i].x * kb.x + qa[i].y * kb.y + qa[i].z * kb.z + qa[i].w * kb.w;
            }
        }

#pragma unroll
        for (int j = 0; j < 4; ++j) {
            int gk = k0 + tx * 4 + j;
            bool pd = gk >= blen;
#pragma unroll
            for (int i = 0; i < 4; ++i) {
                int gq = q0 + ty * 4 + i;
                if (pd || gk > gq) s[i][j] = -1e30f;
            }
        }

#pragma unroll
        for (int i = 0; i < 4; ++i) {
            float mx = fmaxf(fmaxf(s[i][0], s[i][1]), fmaxf(s[i][2], s[i][3]));
#pragma unroll
            for (int off = 8; off; off >>= 1)
                mx = fmaxf(mx, __shfl_xor_sync(0xffffffffu, mx, off));
            float mnew  = fmaxf(m_i[i], mx);
            float alpha = __expf(m_i[i] - mnew);
            float sum = 0.f;
#pragma unroll
            for (int j = 0; j < 4; ++j) {
                float p = __expf(s[i][j] - mnew);
                s[i][j] = p;
                sum += p;
            }
#pragma unroll
            for (int off = 8; off; off >>= 1)
                sum += __shfl_xor_sync(0xffffffffu, sum, off);
            l_i[i] = l_i[i] * alpha + sum;
            m_i[i] = mnew;
#pragma unroll
            for (int j = 0; j < 4; ++j) O[i][j] *= alpha;
        }

        __syncthreads();
#pragma unroll
        for (int i = 0; i < 4; ++i)
#pragma unroll
            for (int j = 0; j < 4; ++j)
                KPs[(ty * 4 + i) * 64 + tx * 4 + j] = s[i][j];
        __syncthreads();

#pragma unroll
        for (int k4 = 0; k4 < 16; ++k4) {
            float p[4][4];
#pragma unroll
            for (int i = 0; i < 4; ++i)
                *(float4*)&p[i][0] = *(const float4*)&KPs[(ty * 4 + i) * 64 + (k4 << 2)];
            float vr[4][4];
#pragma unroll
            for (int kk = 0; kk < 4; ++kk)
                *(float4*)&vr[kk][0] = *(const float4*)&Vs[(k4 * 4 + kk) * 64 + tx * 4];
#pragma unroll
            for (int i = 0; i < 4; ++i)
#pragma unroll
                for (int j = 0; j < 4; ++j)
                    O[i][j] += p[i][0] * vr[0][j] + p[i][1] * vr[1][j]
                             + p[i][2] * vr[2][j] + p[i][3] * vr[3][j];
        }
    }

#pragma unroll
    for (int i = 0; i < 4; ++i) {
        float inv = 1.f / l_i[i];
#pragma unroll
        for (int j = 0; j < 4; ++j)
            out[(size_t)(b * 1024 + q0 + ty * 4 + i) * 1024 + h * 64 + tx * 4 + j] = O[i][j] * inv;
    }
}

// ---------------- LayerNorm ------------------------------------------------
__global__ __launch_bounds__(256) void ln_kernel(
    const float* __restrict__ X, const float* __restrict__ w,
    const float* __restrict__ bb, float* __restrict__ Y)
{
    const int row = blockIdx.x;
    const int t   = threadIdx.x;
    float4 x = *(const float4*)&X[(size_t)row * 1024 + t * 4];
    float s = x.x + x.y + x.z + x.w;
    float q = fmaf(x.x, x.x, fmaf(x.y, x.y, fmaf(x.z, x.z, x.w * x.w)));
#pragma unroll
    for (int off = 16; off; off >>= 1) {
        s += __shfl_xor_sync(0xffffffffu, s, off);
        q += __shfl_xor_sync(0xffffffffu, q, off);
    }
    __shared__ float ss[8], qq[8];
    const int warp = t >> 5, lane = t & 31;
    if (lane == 0) { ss[warp] = s; qq[warp] = q; }
    __syncthreads();
    float S = 0.f, Q2 = 0.f;
#pragma unroll
    for (int i = 0; i < 8; ++i) { S += ss[i]; Q2 += qq[i]; }
    const float mean = S * (1.0f / 1024.0f);
    const float var  = fmaxf(Q2 * (1.0f / 1024.0f) - mean * mean, 0.f);
    const float inv  = rsqrtf(var + 1e-12f);
    float4 wv = *(const float4*)&w[t * 4];
    float4 bv = *(const float4*)&bb[t * 4];
    float4 y;
    y.x = wv.x * (x.x - mean) * inv + bv.x;
    y.y = wv.y * (x.y - mean) * inv + bv.y;
    y.z = wv.z * (x.z - mean) * inv + bv.z;
    y.w = wv.w * (x.w - mean) * inv + bv.w;
    *(float4*)&Y[(size_t)row * 1024 + t * 4] = y;
}

// ---------------- launch ----------------------------------------------------
extern "C" void kernel_launch(void* const* d_in, const int* in_sizes, int n_in,
                              void* d_out, int out_size)
{
    const float* x     = (const float*)d_in[0];
    const float* in_w  = (const float*)d_in[1];
    const float* in_b  = (const float*)d_in[2];
    const float* out_w = (const float*)d_in[3];
    const float* out_b = (const float*)d_in[4];
    const float* fc1_w = (const float*)d_in[5];
    const float* fc1_b = (const float*)d_in[6];
    const float* fc2_w = (const float*)d_in[7];
    const float* fc2_b = (const float*)d_in[8];
    const float* ln1_w = (const float*)d_in[9];
    const float* ln1_b = (const float*)d_in[10];
    const float* ln2_w = (const float*)d_in[11];
    const float* ln2_b = (const float*)d_in[12];
    const void*  pad   = d_in[13];
    float* out = (float*)d_out;

    float *qkv, *attn, *sbuf, *x1, *ff;
    int* lenv;
    cudaGetSymbolAddress((void**)&qkv,  g_qkv);
    cudaGetSymbolAddress((void**)&attn, g_attn);
    cudaGetSymbolAddress((void**)&sbuf, g_s);
    cudaGetSymbolAddress((void**)&x1,   g_x1);
    cudaGetSymbolAddress((void**)&ff,   g_ff);
    cudaGetSymbolAddress((void**)&lenv, g_len);

    mask_len_kernel<<<1, 256>>>(pad);
    // 1) qkv = x @ in_w^T + in_b           [8192, 3072]
    tgemm_kernel<0><<<dim3(3072 / 128, 8192 / 128), 256>>>(x, in_w, in_b, nullptr, qkv, 1024, 3072);
    // 2) attention -> attn                 [8192, 1024]
    attn_kernel<<<dim3(16, 16, 8), 256>>>(qkv, lenv, attn);
    // 3) s1 = attn @ out_w^T + out_b + x   [8192, 1024]
    tgemm_kernel<1><<<dim3(1024 / 128, 8192 / 128), 256>>>(attn, out_w, out_b, x, sbuf, 1024, 1024);
    // 4) x1 = LN1(s1)
    ln_kernel<<<8192, 256>>>(sbuf, ln1_w, ln1_b, x1);
    // 5) ff = relu(x1 @ fc1_w^T + fc1_b)   [8192, 4096]
    tgemm_kernel<2><<<dim3(4096 / 128, 8192 / 128), 256>>>(x1, fc1_w, fc1_b, nullptr, ff, 1024, 4096);
    // 6) s2 = ff @ fc2_w^T + fc2_b + x1    [8192, 1024]
    tgemm_kernel<1><<<dim3(1024 / 128, 8192 / 128), 256>>>(ff, fc2_w, fc2_b, x1, sbuf, 4096, 1024);
    // 7) out = LN2(s2)
    ln_kernel<<<8192, 256>>>(sbuf, ln2_w, ln2_b, out);
}

// round 5
// speedup vs baseline: 3.1864x; 1.3740x over previous
#include <cuda_runtime.h>
#include <math.h>
#include <stdint.h>

// Problem dims: B=8, T=1024, E=1024, H=16, HD=64, FF=4096, M = B*T = 8192

// ---------------- scratch (device globals; no allocations allowed) ----------
__device__ float g_qkv[(size_t)8192 * 3072];
__device__ float g_attn[(size_t)8192 * 1024];
__device__ float g_s[(size_t)8192 * 1024];
__device__ float g_x1[(size_t)8192 * 1024];
__device__ float g_ff[(size_t)8192 * 4096];
__device__ int   g_len[8];

// ---------------- padding-mask dtype detection + length extraction ----------
__global__ void mask_len_kernel(const void* mask) {
    __shared__ int sGT1, sEQ1, sF32;
    if (threadIdx.x == 0) { sGT1 = 0; sEQ1 = 0; sF32 = 0; }
    __syncthreads();
    const unsigned int* w = (const unsigned int*)mask;
    int gt1 = 0, eq1 = 0, f32 = 0;
    for (int i = threadIdx.x; i < 2048; i += 256) {
        unsigned int v = w[i];
        if (v == 0x3F800000u)      f32 = 1;
        else if (v == 1u)          eq1 = 1;
        else if (v != 0u)          gt1 = 1;
    }
    if (f32) atomicOr(&sF32, 1);
    if (gt1) atomicOr(&sGT1, 1);
    if (eq1) atomicOr(&sEQ1, 1);
    __syncthreads();
    if (threadIdx.x < 8) {
        const int b = threadIdx.x;
        int len = 1024;
        if (sF32) {
            const float* p = (const float*)mask;
            for (int k = 0; k < 1024; ++k)
                if (p[(size_t)b * 1024 + k] != 0.f) { len = k; break; }
        } else if (sGT1) {
            const unsigned char* p = (const unsigned char*)mask;
            for (int k = 0; k < 1024; ++k)
                if (p[(size_t)b * 1024 + k]) { len = k; break; }
        } else if (sEQ1) {
            const int* p = (const int*)mask;
            for (int k = 0; k < 1024; ++k)
                if (p[(size_t)b * 1024 + k]) { len = k; break; }
        }
        g_len[b] = len;
    }
}

// ---------------- common helpers -------------------------------------------
__device__ __forceinline__ uint32_t f2tf(float x) {
    uint32_t r;
    asm("cvt.rna.tf32.f32 %0, %1;" : "=r"(r) : "f"(x));
    return r;
}
__device__ __forceinline__ void mma_tf32(float* d, const uint32_t* a, const uint32_t* b) {
    asm volatile(
        "mma.sync.aligned.m16n8k8.row.col.f32.tf32.tf32.f32 "
        "{%0,%1,%2,%3}, {%4,%5,%6,%7}, {%8,%9}, {%0,%1,%2,%3};"
        : "+f"(d[0]), "+f"(d[1]), "+f"(d[2]), "+f"(d[3])
        : "r"(a[0]), "r"(a[1]), "r"(a[2]), "r"(a[3]), "r"(b[0]), "r"(b[1]));
}
__device__ __forceinline__ void ldsm4(uint32_t& r0, uint32_t& r1, uint32_t& r2, uint32_t& r3,
                                      uint32_t addr) {
    asm volatile("ldmatrix.sync.aligned.m8n8.x4.shared.b16 {%0,%1,%2,%3}, [%4];"
                 : "=r"(r0), "=r"(r1), "=r"(r2), "=r"(r3) : "r"(addr));
}
__device__ __forceinline__ uint32_t s2u(const void* p) {
    return (uint32_t)__cvta_generic_to_shared(p);
}

// ---------------- tf32 tensor-core GEMM (ldmatrix + double buffer) ----------
// C[M,N] = A[M,K] @ W[N,K]^T + bias (+res/+relu).
// 128x128 tile, kstep 16, 8 warps (4m x 2n), warp tile 32x64.
// SMEM tile [row][16 words], chunk-swizzled: 16B chunk c of row r sits at
// word r*16 + 4*(c ^ ((r>>1)&3)).  STS.128 staging and ldmatrix reads both
// conflict-free.  kk=8 fragments = kk=0 address XOR 32 bytes.
template <int EPI>  // 0: +bias, 1: +bias+residual, 2: +bias+relu
__global__ __launch_bounds__(256, 2) void tgemm_kernel(
    const float* __restrict__ A, const float* __restrict__ W,
    const float* __restrict__ bias, const float* __restrict__ R,
    float* __restrict__ C, int Ksz, int Nsz)
{
    __shared__ uint32_t As[2][128 * 16];
    __shared__ uint32_t Bs[2][128 * 16];

    const int tid  = threadIdx.x;
    const int lane = tid & 31;
    const int warp = tid >> 5;
    const int wm   = warp & 3;
    const int wn   = warp >> 2;
    const int m0   = blockIdx.y * 128;
    const int n0   = blockIdx.x * 128;

    // staging map: rows sr, sr+64; 16B chunk sc
    const int sr = tid >> 2;
    const int sc = tid & 3;
    const uint32_t w0 = sr * 16 + 4 * (sc ^ ((sr >> 1) & 3));   // +1024 for row+64

    const float* Ap0 = A + (size_t)(m0 + sr) * Ksz + sc * 4;
    const float* Ap1 = A + (size_t)(m0 + sr + 64) * Ksz + sc * 4;
    const float* Wp0 = W + (size_t)(n0 + sr) * Ksz + sc * 4;
    const float* Wp1 = W + (size_t)(n0 + sr + 64) * Ksz + sc * 4;

    // fragment ldmatrix base addresses (buffer 0, kk=0)
    const int mat = lane >> 3, rr = lane & 7;
    const int ar  = wm * 32 + (mat & 1) * 8 + rr;
    const int ac  = mat >> 1;
    const uint32_t aA = s2u(&As[0][0]) + (ar * 16 + 4 * (ac ^ ((ar >> 1) & 3))) * 4;
    const int br  = wn * 64 + (mat >> 1) * 8 + rr;
    const int bc  = mat & 1;
    const uint32_t aB = s2u(&Bs[0][0]) + (br * 16 + 4 * (bc ^ ((br >> 1) & 3))) * 4;

    float acc[2][8][4];
#pragma unroll
    for (int i = 0; i < 2; ++i)
#pragma unroll
        for (int j = 0; j < 8; ++j)
#pragma unroll
            for (int r = 0; r < 4; ++r) acc[i][j][r] = 0.f;

    float4 pa0 = *(const float4*)Ap0;
    float4 pa1 = *(const float4*)Ap1;
    float4 pb0 = *(const float4*)Wp0;
    float4 pb1 = *(const float4*)Wp1;

    // stage k=0 into buffer 0
    {
        uint32_t t[4];
        t[0]=f2tf(pa0.x); t[1]=f2tf(pa0.y); t[2]=f2tf(pa0.z); t[3]=f2tf(pa0.w);
        *(uint4*)&As[0][w0] = *(uint4*)t;
        t[0]=f2tf(pa1.x); t[1]=f2tf(pa1.y); t[2]=f2tf(pa1.z); t[3]=f2tf(pa1.w);
        *(uint4*)&As[0][w0 + 1024] = *(uint4*)t;
        t[0]=f2tf(pb0.x); t[1]=f2tf(pb0.y); t[2]=f2tf(pb0.z); t[3]=f2tf(pb0.w);
        *(uint4*)&Bs[0][w0] = *(uint4*)t;
        t[0]=f2tf(pb1.x); t[1]=f2tf(pb1.y); t[2]=f2tf(pb1.z); t[3]=f2tf(pb1.w);
        *(uint4*)&Bs[0][w0 + 1024] = *(uint4*)t;
    }
    __syncthreads();

    for (int k0 = 0; k0 < Ksz; k0 += 16) {
        const int  buf  = (k0 >> 4) & 1;
        const bool more = (k0 + 16) < Ksz;
        if (more) {
            pa0 = *(const float4*)(Ap0 + k0 + 16);
            pa1 = *(const float4*)(Ap1 + k0 + 16);
            pb0 = *(const float4*)(Wp0 + k0 + 16);
            pb1 = *(const float4*)(Wp1 + k0 + 16);
        }

        const uint32_t aAb = aA + buf * 8192;
        const uint32_t aBb = aB + buf * 8192;
#pragma unroll
        for (int kk8 = 0; kk8 < 2; ++kk8) {
            const uint32_t xo = kk8 << 5;        // kk=8 -> XOR 32 bytes
            uint32_t af0[4], af1[4];
            ldsm4(af0[0], af0[1], af0[2], af0[3], aAb ^ xo);
            ldsm4(af1[0], af1[1], af1[2], af1[3], (aAb + 1024) ^ xo);
#pragma unroll
            for (int jp = 0; jp < 4; ++jp) {
                uint32_t bf[4];
                ldsm4(bf[0], bf[1], bf[2], bf[3], (aBb + jp * 1024) ^ xo);
                mma_tf32(acc[0][2 * jp],     af0, &bf[0]);
                mma_tf32(acc[1][2 * jp],     af1, &bf[0]);
                mma_tf32(acc[0][2 * jp + 1], af0, &bf[2]);
                mma_tf32(acc[1][2 * jp + 1], af1, &bf[2]);
            }
        }

        if (more) {
            const int nb = buf ^ 1;
            uint32_t t[4];
            t[0]=f2tf(pa0.x); t[1]=f2tf(pa0.y); t[2]=f2tf(pa0.z); t[3]=f2tf(pa0.w);
            *(uint4*)&As[nb][w0] = *(uint4*)t;
            t[0]=f2tf(pa1.x); t[1]=f2tf(pa1.y); t[2]=f2tf(pa1.z); t[3]=f2tf(pa1.w);
            *(uint4*)&As[nb][w0 + 1024] = *(uint4*)t;
            t[0]=f2tf(pb0.x); t[1]=f2tf(pb0.y); t[2]=f2tf(pb0.z); t[3]=f2tf(pb0.w);
            *(uint4*)&Bs[nb][w0] = *(uint4*)t;
            t[0]=f2tf(pb1.x); t[1]=f2tf(pb1.y); t[2]=f2tf(pb1.z); t[3]=f2tf(pb1.w);
            *(uint4*)&Bs[nb][w0 + 1024] = *(uint4*)t;
        }
        __syncthreads();
    }

    // epilogue
#pragma unroll
    for (int i = 0; i < 2; ++i) {
        int row = m0 + wm * 32 + i * 16 + (lane >> 2);
#pragma unroll
        for (int j = 0; j < 8; ++j) {
            int col = n0 + wn * 64 + j * 8 + (lane & 3) * 2;
            float b0v = bias[col], b1v = bias[col + 1];
            size_t o0 = (size_t)row * Nsz + col;
            size_t o1 = (size_t)(row + 8) * Nsz + col;
            float v0 = acc[i][j][0] + b0v, v1 = acc[i][j][1] + b1v;
            float v2 = acc[i][j][2] + b0v, v3 = acc[i][j][3] + b1v;
            if (EPI == 1) {
                v0 += R[o0]; v1 += R[o0 + 1];
                v2 += R[o1]; v3 += R[o1 + 1];
            }
            if (EPI == 2) {
                v0 = fmaxf(v0, 0.f); v1 = fmaxf(v1, 0.f);
                v2 = fmaxf(v2, 0.f); v3 = fmaxf(v3, 0.f);
            }
            float2 q0v = { v0, v1 }, q1v = { v2, v3 };
            *(float2*)&C[o0] = q0v;
            *(float2*)&C[o1] = q1v;
        }
    }
}

// ---------------- attention: tf32-mma flash, per (b, h, 64-query tile) ------
// 128 threads = 4 warps; warp w owns query rows [w*16, w*16+16).
// SMEM tiles 64x64 tf32, chunk-swizzled: 16B chunk c of row r at word
// r*64 + 4*((c&8) | ((c&7) ^ (r&7))).
// Qs: [q][d]  (A of QK^T and base of everything)
// KP: [key][d] for K (B of QK^T), then reused as [q][key] for P (A of PV)
// Vt: [d][key] transposed V (B of PV)
__device__ __forceinline__ uint32_t aswz(uint32_t base, int row, int chunk) {
    int pos = (chunk & 8) | ((chunk & 7) ^ (row & 7));
    return base + (row * 64 + 4 * pos) * 4;
}

__global__ __launch_bounds__(128) void attn_kernel(
    const float* __restrict__ qkv, const int* __restrict__ lenv,
    float* __restrict__ out)
{
    __shared__ uint32_t Qs[64 * 64];
    __shared__ uint32_t KP[64 * 64];
    __shared__ uint32_t Vt[64 * 64];

    const int tid  = threadIdx.x;
    const int lane = tid & 31;
    const int wrp  = tid >> 5;        // 0..3
    const int b    = blockIdx.z;
    const int h    = blockIdx.y;
    const int qt   = blockIdx.x;
    const int q0   = qt * 64;
    const int blen = lenv[b];
    const float scale = 0.125f;

    const uint32_t Qb = s2u(Qs), Kb = s2u(KP), Vb = s2u(Vt);

    // load Q tile (pre-scaled, tf32)
    for (int i = tid; i < 64 * 16; i += 128) {
        int r = i >> 4, c4 = i & 15;
        float4 v = *(const float4*)&qkv[(size_t)(b * 1024 + q0 + r) * 3072 + h * 64 + c4 * 4];
        int pos = (c4 & 8) | ((c4 & 7) ^ (r & 7));
        uint32_t t[4] = { f2tf(v.x * scale), f2tf(v.y * scale),
                          f2tf(v.z * scale), f2tf(v.w * scale) };
        *(uint4*)&Qs[r * 64 + 4 * pos] = *(uint4*)t;
    }

    // per-lane fragment constants
    const int mat = lane >> 3, rr = lane & 7;
    const int g   = lane >> 2;        // row-in-atom group
    const int q2  = lane & 3;
    // A-frag row (within a 16-row atom) for ldmatrix: atombase + (mat&1)*8 + rr
    const int aRowQ = wrp * 16 + (mat & 1) * 8 + rr;       // Qs / P rows
    const int cbitA = mat >> 1;                            // chunk bit for A
    const int cbitB = mat & 1;                             // chunk bit for B
    const int bRowOff = (mat >> 1) * 8 + rr;               // B row within 16-row pair

    float O[8][4];
    float m0r = -1e30f, m1r = -1e30f, l0r = 0.f, l1r = 0.f;
#pragma unroll
    for (int j = 0; j < 8; ++j)
#pragma unroll
        for (int r = 0; r < 4; ++r) O[j][r] = 0.f;

    const int ktmax = qt;     // causal tile bound
    for (int kt = 0; kt <= ktmax && kt * 64 < blen; ++kt) {
        const int k0 = kt * 64;
        __syncthreads();      // prior-iter readers of KP/Vt done (also Q stores, kt=0)

        // K tile -> KP [key][d]
        for (int i = tid; i < 64 * 16; i += 128) {
            int r = i >> 4, c4 = i & 15;
            float4 v = *(const float4*)&qkv[(size_t)(b * 1024 + k0 + r) * 3072 + 1024 + h * 64 + c4 * 4];
            int pos = (c4 & 8) | ((c4 & 7) ^ (r & 7));
            uint32_t t[4] = { f2tf(v.x), f2tf(v.y), f2tf(v.z), f2tf(v.w) };
            *(uint4*)&KP[r * 64 + 4 * pos] = *(uint4*)t;
        }
        // V tile -> Vt [d][key] (transposed; lane==key keeps STS conflict-free)
        for (int i = tid; i < 64 * 16; i += 128) {
            int key = i & 63, dc = i >> 6;
            float4 v = *(const float4*)&qkv[(size_t)(b * 1024 + k0 + key) * 3072 + 2048 + h * 64 + dc * 4];
            int kc = key >> 2, kb = key & 3;
            float e[4] = { v.x, v.y, v.z, v.w };
#pragma unroll
            for (int s = 0; s < 4; ++s) {
                int d = dc * 4 + s;
                int pos = (kc & 8) | ((kc & 7) ^ (d & 7));
                Vt[d * 64 + 4 * pos + kb] = f2tf(e[s]);
            }
        }
        __syncthreads();

        // ---- S = Q @ K^T : warp tile 16x64, k = d = 64 ----
        float s[8][4];
#pragma unroll
        for (int j = 0; j < 8; ++j)
#pragma unroll
            for (int r = 0; r < 4; ++r) s[j][r] = 0.f;

#pragma unroll
        for (int kk = 0; kk < 8; ++kk) {      // d chunks of 8
            int ck = kk * 2;
            uint32_t af[4];
            ldsm4(af[0], af[1], af[2], af[3], aswz(Qb, aRowQ, ck + cbitA));
#pragma unroll
            for (int jp = 0; jp < 4; ++jp) {
                uint32_t bf[4];
                ldsm4(bf[0], bf[1], bf[2], bf[3],
                      aswz(Kb, jp * 16 + bRowOff, ck + cbitB));
                mma_tf32(s[2 * jp],     af, &bf[0]);
                mma_tf32(s[2 * jp + 1], af, &bf[2]);
            }
        }

        // ---- mask + online softmax (fragment layout) ----
        const int qr0 = q0 + wrp * 16 + g;
        const int qr1 = qr0 + 8;
#pragma unroll
        for (int j = 0; j < 8; ++j) {
            int c0 = k0 + j * 8 + q2 * 2;
            int c1 = c0 + 1;
            if (c0 > qr0 || c0 >= blen) s[j][0] = -1e30f;
            if (c1 > qr0 || c1 >= blen) s[j][1] = -1e30f;
            if (c0 > qr1 || c0 >= blen) s[j][2] = -1e30f;
            if (c1 > qr1 || c1 >= blen) s[j][3] = -1e30f;
        }
        float mx0 = -1e30f, mx1 = -1e30f;
#pragma unroll
        for (int j = 0; j < 8; ++j) {
            mx0 = fmaxf(mx0, fmaxf(s[j][0], s[j][1]));
            mx1 = fmaxf(mx1, fmaxf(s[j][2], s[j][3]));
        }
        mx0 = fmaxf(mx0, __shfl_xor_sync(0xffffffffu, mx0, 1));
        mx0 = fmaxf(mx0, __shfl_xor_sync(0xffffffffu, mx0, 2));
        mx1 = fmaxf(mx1, __shfl_xor_sync(0xffffffffu, mx1, 1));
        mx1 = fmaxf(mx1, __shfl_xor_sync(0xffffffffu, mx1, 2));
        float mn0 = fmaxf(m0r, mx0), mn1 = fmaxf(m1r, mx1);
        float al0 = __expf(m0r - mn0), al1 = __expf(m1r - mn1);
        float sm0 = 0.f, sm1 = 0.f;
#pragma unroll
        for (int j = 0; j < 8; ++j) {
            s[j][0] = __expf(s[j][0] - mn0);
            s[j][1] = __expf(s[j][1] - mn0);
            s[j][2] = __expf(s[j][2] - mn1);
            s[j][3] = __expf(s[j][3] - mn1);
            sm0 += s[j][0] + s[j][1];
            sm1 += s[j][2] + s[j][3];
        }
        sm0 += __shfl_xor_sync(0xffffffffu, sm0, 1);
        sm0 += __shfl_xor_sync(0xffffffffu, sm0, 2);
        sm1 += __shfl_xor_sync(0xffffffffu, sm1, 1);
        sm1 += __shfl_xor_sync(0xffffffffu, sm1, 2);
        l0r = l0r * al0 + sm0;
        l1r = l1r * al1 + sm1;
        m0r = mn0; m1r = mn1;
#pragma unroll
        for (int j = 0; j < 8; ++j) {
            O[j][0] *= al0; O[j][1] *= al0;
            O[j][2] *= al1; O[j][3] *= al1;
        }

        __syncthreads();      // all warps done reading K from KP

        // ---- store P into KP as [q][key] (tf32) ----
#pragma unroll
        for (int j = 0; j < 8; ++j) {
            int key = j * 8 + q2 * 2;
            int kc  = key >> 2;
            int pos = (kc & 8) | ((kc & 7) ^ (g & 7));
            int wrd = (wrp * 16 + g) * 64 + 4 * pos + (key & 3);
            uint32_t p0[2] = { f2tf(s[j][0]), f2tf(s[j][1]) };
            *(uint2*)&KP[wrd] = *(uint2*)p0;
            uint32_t p1[2] = { f2tf(s[j][2]), f2tf(s[j][3]) };
            *(uint2*)&KP[wrd + 8 * 64] = *(uint2*)p1;
        }
        __syncthreads();

        // ---- O += P @ V : k = keys = 64 ----
#pragma unroll
        for (int kk = 0; kk < 8; ++kk) {
            int ck = kk * 2;
            uint32_t af[4];
            ldsm4(af[0], af[1], af[2], af[3], aswz(Kb, aRowQ, ck + cbitA));
#pragma unroll
            for (int jp = 0; jp < 4; ++jp) {
                uint32_t bf[4];
                ldsm4(bf[0], bf[1], bf[2], bf[3],
                      aswz(Vb, jp * 16 + bRowOff, ck + cbitB));
                mma_tf32(O[2 * jp],     af, &bf[0]);
                mma_tf32(O[2 * jp + 1], af, &bf[2]);
            }
        }
    }

    // epilogue: normalize, write [B*T, E]
    const float inv0 = 1.f / l0r, inv1 = 1.f / l1r;
    const int row0 = b * 1024 + q0 + wrp * 16 + g;
#pragma unroll
    for (int j = 0; j < 8; ++j) {
        int d = h * 64 + j * 8 + q2 * 2;
        float2 v0 = { O[j][0] * inv0, O[j][1] * inv0 };
        float2 v1 = { O[j][2] * inv1, O[j][3] * inv1 };
        *(float2*)&out[(size_t)row0 * 1024 + d] = v0;
        *(float2*)&out[(size_t)(row0 + 8) * 1024 + d] = v1;
    }
}

// ---------------- LayerNorm ------------------------------------------------
__global__ __launch_bounds__(256) void ln_kernel(
    const float* __restrict__ X, const float* __restrict__ w,
    const float* __restrict__ bb, float* __restrict__ Y)
{
    const int row = blockIdx.x;
    const int t   = threadIdx.x;
    float4 x = *(const float4*)&X[(size_t)row * 1024 + t * 4];
    float s = x.x + x.y + x.z + x.w;
    float q = fmaf(x.x, x.x, fmaf(x.y, x.y, fmaf(x.z, x.z, x.w * x.w)));
#pragma unroll
    for (int off = 16; off; off >>= 1) {
        s += __shfl_xor_sync(0xffffffffu, s, off);
        q += __shfl_xor_sync(0xffffffffu, q, off);
    }
    __shared__ float ss[8], qq[8];
    const int warp = t >> 5, lane = t & 31;
    if (lane == 0) { ss[warp] = s; qq[warp] = q; }
    __syncthreads();
    float S = 0.f, Q2 = 0.f;
#pragma unroll
    for (int i = 0; i < 8; ++i) { S += ss[i]; Q2 += qq[i]; }
    const float mean = S * (1.0f / 1024.0f);
    const float var  = fmaxf(Q2 * (1.0f / 1024.0f) - mean * mean, 0.f);
    const float inv  = rsqrtf(var + 1e-12f);
    float4 wv = *(const float4*)&w[t * 4];
    float4 bv = *(const float4*)&bb[t * 4];
    float4 y;
    y.x = wv.x * (x.x - mean) * inv + bv.x;
    y.y = wv.y * (x.y - mean) * inv + bv.y;
    y.z = wv.z * (x.z - mean) * inv + bv.z;
    y.w = wv.w * (x.w - mean) * inv + bv.w;
    *(float4*)&Y[(size_t)row * 1024 + t * 4] = y;
}

// ---------------- launch ----------------------------------------------------
extern "C" void kernel_launch(void* const* d_in, const int* in_sizes, int n_in,
                              void* d_out, int out_size)
{
    const float* x     = (const float*)d_in[0];
    const float* in_w  = (const float*)d_in[1];
    const float* in_b  = (const float*)d_in[2];
    const float* out_w = (const float*)d_in[3];
    const float* out_b = (const float*)d_in[4];
    const float* fc1_w = (const float*)d_in[5];
    const float* fc1_b = (const float*)d_in[6];
    const float* fc2_w = (const float*)d_in[7];
    const float* fc2_b = (const float*)d_in[8];
    const float* ln1_w = (const float*)d_in[9];
    const float* ln1_b = (const float*)d_in[10];
    const float* ln2_w = (const float*)d_in[11];
    const float* ln2_b = (const float*)d_in[12];
    const void*  pad   = d_in[13];
    float* out = (float*)d_out;

    float *qkv, *attn, *sbuf, *x1, *ff;
    int* lenv;
    cudaGetSymbolAddress((void**)&qkv,  g_qkv);
    cudaGetSymbolAddress((void**)&attn, g_attn);
    cudaGetSymbolAddress((void**)&sbuf, g_s);
    cudaGetSymbolAddress((void**)&x1,   g_x1);
    cudaGetSymbolAddress((void**)&ff,   g_ff);
    cudaGetSymbolAddress((void**)&lenv, g_len);

    mask_len_kernel<<<1, 256>>>(pad);
    // 1) qkv = x @ in_w^T + in_b           [8192, 3072]
    tgemm_kernel<0><<<dim3(3072 / 128, 8192 / 128), 256>>>(x, in_w, in_b, nullptr, qkv, 1024, 3072);
    // 2) attention -> attn                 [8192, 1024]
    attn_kernel<<<dim3(16, 16, 8), 128>>>(qkv, lenv, attn);
    // 3) s1 = attn @ out_w^T + out_b + x   [8192, 1024]
    tgemm_kernel<1><<<dim3(1024 / 128, 8192 / 128), 256>>>(attn, out_w, out_b, x, sbuf, 1024, 1024);
    // 4) x1 = LN1(s1)
    ln_kernel<<<8192, 256>>>(sbuf, ln1_w, ln1_b, x1);
    // 5) ff = relu(x1 @ fc1_w^T + fc1_b)   [8192, 4096]
    tgemm_kernel<2><<<dim3(4096 / 128, 8192 / 128), 256>>>(x1, fc1_w, fc1_b, nullptr, ff, 1024, 4096);
    // 6) s2 = ff @ fc2_w^T + fc2_b + x1    [8192, 1024]
    tgemm_kernel<1><<<dim3(1024 / 128, 8192 / 128), 256>>>(ff, fc2_w, fc2_b, x1, sbuf, 4096, 1024);
    // 7) out = LN2(s2)
    ln_kernel<<<8192, 256>>>(sbuf, ln2_w, ln2_b, out);
}

// round 7
// speedup vs baseline: 4.4226x; 1.3880x over previous
#include <cuda_runtime.h>
#include <math.h>
#include <stdint.h>

// Problem dims: B=8, T=1024, E=1024, H=16, HD=64, FF=4096, M = B*T = 8192

// ---------------- scratch (device globals; no allocations allowed) ----------
__device__ float g_qkv[(size_t)8192 * 3072];
__device__ float g_attn[(size_t)8192 * 1024];
__device__ float g_s[(size_t)8192 * 1024];
__device__ float g_x1[(size_t)8192 * 1024];
__device__ float g_ff[(size_t)8192 * 4096];
__device__ int   g_len[8];

// ---------------- padding-mask dtype detection + length extraction ----------
__global__ void mask_len_kernel(const void* mask) {
    __shared__ int sGT1, sEQ1, sF32;
    if (threadIdx.x == 0) { sGT1 = 0; sEQ1 = 0; sF32 = 0; }
    __syncthreads();
    const unsigned int* w = (const unsigned int*)mask;
    int gt1 = 0, eq1 = 0, f32 = 0;
    for (int i = threadIdx.x; i < 2048; i += 256) {
        unsigned int v = w[i];
        if (v == 0x3F800000u)      f32 = 1;
        else if (v == 1u)          eq1 = 1;
        else if (v != 0u)          gt1 = 1;
    }
    if (f32) atomicOr(&sF32, 1);
    if (gt1) atomicOr(&sGT1, 1);
    if (eq1) atomicOr(&sEQ1, 1);
    __syncthreads();
    if (threadIdx.x < 8) {
        const int b = threadIdx.x;
        int len = 1024;
        if (sF32) {
            const float* p = (const float*)mask;
            for (int k = 0; k < 1024; ++k)
                if (p[(size_t)b * 1024 + k] != 0.f) { len = k; break; }
        } else if (sGT1) {
            const unsigned char* p = (const unsigned char*)mask;
            for (int k = 0; k < 1024; ++k)
                if (p[(size_t)b * 1024 + k]) { len = k; break; }
        } else if (sEQ1) {
            const int* p = (const int*)mask;
            for (int k = 0; k < 1024; ++k)
                if (p[(size_t)b * 1024 + k]) { len = k; break; }
        }
        g_len[b] = len;
    }
}

// ---------------- common helpers -------------------------------------------
__device__ __forceinline__ uint32_t f2tf(float x) {
    uint32_t r;
    asm("cvt.rna.tf32.f32 %0, %1;" : "=r"(r) : "f"(x));
    return r;
}
__device__ __forceinline__ void mma_tf32(float* d, const uint32_t* a, const uint32_t* b) {
    asm volatile(
        "mma.sync.aligned.m16n8k8.row.col.f32.tf32.tf32.f32 "
        "{%0,%1,%2,%3}, {%4,%5,%6,%7}, {%8,%9}, {%0,%1,%2,%3};"
        : "+f"(d[0]), "+f"(d[1]), "+f"(d[2]), "+f"(d[3])
        : "r"(a[0]), "r"(a[1]), "r"(a[2]), "r"(a[3]), "r"(b[0]), "r"(b[1]));
}
__device__ __forceinline__ void ldsm4(uint32_t& r0, uint32_t& r1, uint32_t& r2, uint32_t& r3,
                                      uint32_t addr) {
    asm volatile("ldmatrix.sync.aligned.m8n8.x4.shared.b16 {%0,%1,%2,%3}, [%4];"
                 : "=r"(r0), "=r"(r1), "=r"(r2), "=r"(r3) : "r"(addr));
}
__device__ __forceinline__ uint32_t s2u(const void* p) {
    return (uint32_t)__cvta_generic_to_shared(p);
}
__device__ __forceinline__ void cpasync16(uint32_t dst, const void* src) {
    asm volatile("cp.async.cg.shared.global [%0], [%1], 16;"
                 :: "r"(dst), "l"(src) : "memory");
}

// ---------------- tf32 tensor-core GEMM (cp.async 4-stage + ldmatrix) -------
// C[M,N] = A[M,K] @ W[N,K]^T + bias (+res/+relu).
// 128x128 tile, kstep 16, 8 warps (4m x 2n), warp tile 32x64.
// Raw fp32 is staged to SMEM by cp.async (LDGSTS); HMMA.TF32 truncates the
// operands to tf32 in hardware (cuBLAS tf32 fast path behavior) — no cvt.
// SMEM tile [row][16 words], chunk-swizzled: 16B chunk c of row r at word
// r*16 + 4*(c ^ ((r>>1)&3)).  Stage layout: stage s = s*16KB, A at +0 (8KB),
// B at +8KB.  Pipeline: 4 stages, commit per k-step, wait_group 2.
template <int EPI>  // 0: +bias, 1: +bias+residual, 2: +bias+relu
__global__ __launch_bounds__(256, 2) void tgemm_kernel(
    const float* __restrict__ A, const float* __restrict__ W,
    const float* __restrict__ bias, const float* __restrict__ R,
    float* __restrict__ C, int Ksz, int Nsz)
{
    extern __shared__ uint32_t smem[];   // 4 stages x 16KB = 64KB
    const uint32_t sbase = s2u(smem);

    const int tid  = threadIdx.x;
    const int lane = tid & 31;
    const int warp = tid >> 5;
    const int wm   = warp & 3;
    const int wn   = warp >> 2;
    const int m0   = blockIdx.y * 128;
    const int n0   = blockIdx.x * 128;

    // staging map: rows sr, sr+64, 16B chunk sc, for both A and B
    const int sr = tid >> 2;             // 0..63
    const int sc = tid & 3;
    const uint32_t swz = 4 * (sc ^ ((sr >> 1) & 3));   // same for sr and sr+64
    const uint32_t dA0 = (sr * 16 + swz) * 4;
    const uint32_t dA1 = ((sr + 64) * 16 + swz) * 4;

    const float* Ap0 = A + (size_t)(m0 + sr) * Ksz + sc * 4;
    const float* Ap1 = A + (size_t)(m0 + sr + 64) * Ksz + sc * 4;
    const float* Wp0 = W + (size_t)(n0 + sr) * Ksz + sc * 4;
    const float* Wp1 = W + (size_t)(n0 + sr + 64) * Ksz + sc * 4;

    // fragment ldmatrix base offsets (stage 0)
    const int mat = lane >> 3, rr = lane & 7;
    const int ar  = wm * 32 + (mat & 1) * 8 + rr;
    const int ac  = mat >> 1;
    const uint32_t aA = sbase + (ar * 16 + 4 * (ac ^ ((ar >> 1) & 3))) * 4;
    const int br  = wn * 64 + (mat >> 1) * 8 + rr;
    const int bc  = mat & 1;
    const uint32_t aB = sbase + 8192 + (br * 16 + 4 * (bc ^ ((br >> 1) & 3))) * 4;

    float acc[2][8][4];
#pragma unroll
    for (int i = 0; i < 2; ++i)
#pragma unroll
        for (int j = 0; j < 8; ++j)
#pragma unroll
            for (int r = 0; r < 4; ++r) acc[i][j][r] = 0.f;

    const int KT = Ksz >> 4;             // k-steps of 16

    // prologue: stages 0..2
#pragma unroll
    for (int p = 0; p < 3; ++p) {
        const uint32_t st = sbase + p * 16384;
        cpasync16(st + dA0,        Ap0 + p * 16);
        cpasync16(st + dA1,        Ap1 + p * 16);
        cpasync16(st + 8192 + dA0, Wp0 + p * 16);
        cpasync16(st + 8192 + dA1, Wp1 + p * 16);
        asm volatile("cp.async.commit_group;" ::: "memory");
    }

    for (int kt = 0; kt < KT; ++kt) {
        asm volatile("cp.async.wait_group 2;" ::: "memory");
        __syncthreads();

        // issue stage kt+3 (buffer (kt+3)&3 == (kt-1)&3, reads done pre-barrier)
        if (kt + 3 < KT) {
            const uint32_t st = sbase + ((kt + 3) & 3) * 16384;
            cpasync16(st + dA0,        Ap0 + (kt + 3) * 16);
            cpasync16(st + dA1,        Ap1 + (kt + 3) * 16);
            cpasync16(st + 8192 + dA0, Wp0 + (kt + 3) * 16);
            cpasync16(st + 8192 + dA1, Wp1 + (kt + 3) * 16);
        }
        asm volatile("cp.async.commit_group;" ::: "memory");

        const uint32_t off = (kt & 3) * 16384;
        const uint32_t aAb = aA + off;
        const uint32_t aBb = aB + off;
#pragma unroll
        for (int kk8 = 0; kk8 < 2; ++kk8) {
            const uint32_t xo = kk8 << 5;        // kk=8 -> XOR 32 bytes
            uint32_t af0[4], af1[4];
            ldsm4(af0[0], af0[1], af0[2], af0[3], aAb ^ xo);
            ldsm4(af1[0], af1[1], af1[2], af1[3], (aAb + 1024) ^ xo);
#pragma unroll
            for (int jp = 0; jp < 4; ++jp) {
                uint32_t bf[4];
                ldsm4(bf[0], bf[1], bf[2], bf[3], (aBb + jp * 1024) ^ xo);
                mma_tf32(acc[0][2 * jp],     af0, &bf[0]);
                mma_tf32(acc[1][2 * jp],     af1, &bf[0]);
                mma_tf32(acc[0][2 * jp + 1], af0, &bf[2]);
                mma_tf32(acc[1][2 * jp + 1], af1, &bf[2]);
            }
        }
    }

    // epilogue
#pragma unroll
    for (int i = 0; i < 2; ++i) {
        int row = m0 + wm * 32 + i * 16 + (lane >> 2);
#pragma unroll
        for (int j = 0; j < 8; ++j) {
            int col = n0 + wn * 64 + j * 8 + (lane & 3) * 2;
            float b0v = bias[col], b1v = bias[col + 1];
            size_t o0 = (size_t)row * Nsz + col;
            size_t o1 = (size_t)(row + 8) * Nsz + col;
            float v0 = acc[i][j][0] + b0v, v1 = acc[i][j][1] + b1v;
            float v2 = acc[i][j][2] + b0v, v3 = acc[i][j][3] + b1v;
            if (EPI == 1) {
                v0 += R[o0]; v1 += R[o0 + 1];
                v2 += R[o1]; v3 += R[o1 + 1];
            }
            if (EPI == 2) {
                v0 = fmaxf(v0, 0.f); v1 = fmaxf(v1, 0.f);
                v2 = fmaxf(v2, 0.f); v3 = fmaxf(v3, 0.f);
            }
            float2 q0v = { v0, v1 }, q1v = { v2, v3 };
            *(float2*)&C[o0] = q0v;
            *(float2*)&C[o1] = q1v;
        }
    }
}

// ---------------- attention: tf32-mma flash, per (b, h, 64-query tile) ------
__device__ __forceinline__ uint32_t aswz(uint32_t base, int row, int chunk) {
    int pos = (chunk & 8) | ((chunk & 7) ^ (row & 7));
    return base + (row * 64 + 4 * pos) * 4;
}

__global__ __launch_bounds__(128) void attn_kernel(
    const float* __restrict__ qkv, const int* __restrict__ lenv,
    float* __restrict__ out)
{
    __shared__ uint32_t Qs[64 * 64];
    __shared__ uint32_t KP[64 * 64];
    __shared__ uint32_t Vt[64 * 64];

    const int tid  = threadIdx.x;
    const int lane = tid & 31;
    const int wrp  = tid >> 5;
    const int b    = blockIdx.z;
    const int h    = blockIdx.y;
    const int qt   = blockIdx.x;
    const int q0   = qt * 64;
    const int blen = lenv[b];
    const float scale = 0.125f;

    const uint32_t Qb = s2u(Qs), Kb = s2u(KP), Vb = s2u(Vt);

    for (int i = tid; i < 64 * 16; i += 128) {
        int r = i >> 4, c4 = i & 15;
        float4 v = *(const float4*)&qkv[(size_t)(b * 1024 + q0 + r) * 3072 + h * 64 + c4 * 4];
        int pos = (c4 & 8) | ((c4 & 7) ^ (r & 7));
        uint32_t t[4] = { f2tf(v.x * scale), f2tf(v.y * scale),
                          f2tf(v.z * scale), f2tf(v.w * scale) };
        *(uint4*)&Qs[r * 64 + 4 * pos] = *(uint4*)t;
    }

    const int mat = lane >> 3, rr = lane & 7;
    const int g   = lane >> 2;
    const int q2  = lane & 3;
    const int aRowQ = wrp * 16 + (mat & 1) * 8 + rr;
    const int cbitA = mat >> 1;
    const int cbitB = mat & 1;
    const int bRowOff = (mat >> 1) * 8 + rr;

    float O[8][4];
    float m0r = -1e30f, m1r = -1e30f, l0r = 0.f, l1r = 0.f;
#pragma unroll
    for (int j = 0; j < 8; ++j)
#pragma unroll
        for (int r = 0; r < 4; ++r) O[j][r] = 0.f;

    const int ktmax = qt;
    for (int kt = 0; kt <= ktmax && kt * 64 < blen; ++kt) {
        const int k0 = kt * 64;
        __syncthreads();

        for (int i = tid; i < 64 * 16; i += 128) {
            int r = i >> 4, c4 = i & 15;
            float4 v = *(const float4*)&qkv[(size_t)(b * 1024 + k0 + r) * 3072 + 1024 + h * 64 + c4 * 4];
            int pos = (c4 & 8) | ((c4 & 7) ^ (r & 7));
            uint32_t t[4] = { f2tf(v.x), f2tf(v.y), f2tf(v.z), f2tf(v.w) };
            *(uint4*)&KP[r * 64 + 4 * pos] = *(uint4*)t;
        }
        for (int i = tid; i < 64 * 16; i += 128) {
            int key = i & 63, dc = i >> 6;
            float4 v = *(const float4*)&qkv[(size_t)(b * 1024 + k0 + key) * 3072 + 2048 + h * 64 + dc * 4];
            int kc = key >> 2, kb = key & 3;
            float e[4] = { v.x, v.y, v.z, v.w };
#pragma unroll
            for (int s = 0; s < 4; ++s) {
                int d = dc * 4 + s;
                int pos = (kc & 8) | ((kc & 7) ^ (d & 7));
                Vt[d * 64 + 4 * pos + kb] = f2tf(e[s]);
            }
        }
        __syncthreads();

        float s[8][4];
#pragma unroll
        for (int j = 0; j < 8; ++j)
#pragma unroll
            for (int r = 0; r < 4; ++r) s[j][r] = 0.f;

#pragma unroll
        for (int kk = 0; kk < 8; ++kk) {
            int ck = kk * 2;
            uint32_t af[4];
            ldsm4(af[0], af[1], af[2], af[3], aswz(Qb, aRowQ, ck + cbitA));
#pragma unroll
            for (int jp = 0; jp < 4; ++jp) {
                uint32_t bf[4];
                ldsm4(bf[0], bf[1], bf[2], bf[3],
                      aswz(Kb, jp * 16 + bRowOff, ck + cbitB));
                mma_tf32(s[2 * jp],     af, &bf[0]);
                mma_tf32(s[2 * jp + 1], af, &bf[2]);
            }
        }

        const int qr0 = q0 + wrp * 16 + g;
        const int qr1 = qr0 + 8;
#pragma unroll
        for (int j = 0; j < 8; ++j) {
            int c0 = k0 + j * 8 + q2 * 2;
            int c1 = c0 + 1;
            if (c0 > qr0 || c0 >= blen) s[j][0] = -1e30f;
            if (c1 > qr0 || c1 >= blen) s[j][1] = -1e30f;
            if (c0 > qr1 || c0 >= blen) s[j][2] = -1e30f;
            if (c1 > qr1 || c1 >= blen) s[j][3] = -1e30f;
        }
        float mx0 = -1e30f, mx1 = -1e30f;
#pragma unroll
        for (int j = 0; j < 8; ++j) {
            mx0 = fmaxf(mx0, fmaxf(s[j][0], s[j][1]));
            mx1 = fmaxf(mx1, fmaxf(s[j][2], s[j][3]));
        }
        mx0 = fmaxf(mx0, __shfl_xor_sync(0xffffffffu, mx0, 1));
        mx0 = fmaxf(mx0, __shfl_xor_sync(0xffffffffu, mx0, 2));
        mx1 = fmaxf(mx1, __shfl_xor_sync(0xffffffffu, mx1, 1));
        mx1 = fmaxf(mx1, __shfl_xor_sync(0xffffffffu, mx1, 2));
        float mn0 = fmaxf(m0r, mx0), mn1 = fmaxf(m1r, mx1);
        float al0 = __expf(m0r - mn0), al1 = __expf(m1r - mn1);
        float sm0 = 0.f, sm1 = 0.f;
#pragma unroll
        for (int j = 0; j < 8; ++j) {
            s[j][0] = __expf(s[j][0] - mn0);
            s[j][1] = __expf(s[j][1] - mn0);
            s[j][2] = __expf(s[j][2] - mn1);
            s[j][3] = __expf(s[j][3] - mn1);
            sm0 += s[j][0] + s[j][1];
            sm1 += s[j][2] + s[j][3];
        }
        sm0 += __shfl_xor_sync(0xffffffffu, sm0, 1);
        sm0 += __shfl_xor_sync(0xffffffffu, sm0, 2);
        sm1 += __shfl_xor_sync(0xffffffffu, sm1, 1);
        sm1 += __shfl_xor_sync(0xffffffffu, sm1, 2);
        l0r = l0r * al0 + sm0;
        l1r = l1r * al1 + sm1;
        m0r = mn0; m1r = mn1;
#pragma unroll
        for (int j = 0; j < 8; ++j) {
            O[j][0] *= al0; O[j][1] *= al0;
            O[j][2] *= al1; O[j][3] *= al1;
        }

        __syncthreads();
#pragma unroll
        for (int j = 0; j < 8; ++j) {
            int key = j * 8 + q2 * 2;
            int kc  = key >> 2;
            int pos = (kc & 8) | ((kc & 7) ^ (g & 7));
            int wrd = (wrp * 16 + g) * 64 + 4 * pos + (key & 3);
            uint32_t p0[2] = { f2tf(s[j][0]), f2tf(s[j][1]) };
            *(uint2*)&KP[wrd] = *(uint2*)p0;
            uint32_t p1[2] = { f2tf(s[j][2]), f2tf(s[j][3]) };
            *(uint2*)&KP[wrd + 8 * 64] = *(uint2*)p1;
        }
        __syncthreads();

#pragma unroll
        for (int kk = 0; kk < 8; ++kk) {
            int ck = kk * 2;
            uint32_t af[4];
            ldsm4(af[0], af[1], af[2], af[3], aswz(Kb, aRowQ, ck + cbitA));
#pragma unroll
            for (int jp = 0; jp < 4; ++jp) {
                uint32_t bf[4];
                ldsm4(bf[0], bf[1], bf[2], bf[3],
                      aswz(Vb, jp * 16 + bRowOff, ck + cbitB));
                mma_tf32(O[2 * jp],     af, &bf[0]);
                mma_tf32(O[2 * jp + 1], af, &bf[2]);
            }
        }
    }

    const float inv0 = 1.f / l0r, inv1 = 1.f / l1r;
    const int row0 = b * 1024 + q0 + wrp * 16 + g;
#pragma unroll
    for (int j = 0; j < 8; ++j) {
        int d = h * 64 + j * 8 + q2 * 2;
        float2 v0 = { O[j][0] * inv0, O[j][1] * inv0 };
        float2 v1 = { O[j][2] * inv1, O[j][3] * inv1 };
        *(float2*)&out[(size_t)row0 * 1024 + d] = v0;
        *(float2*)&out[(size_t)(row0 + 8) * 1024 + d] = v1;
    }
}

// ---------------- LayerNorm ------------------------------------------------
__global__ __launch_bounds__(256) void ln_kernel(
    const float* __restrict__ X, const float* __restrict__ w,
    const float* __restrict__ bb, float* __restrict__ Y)
{
    const int row = blockIdx.x;
    const int t   = threadIdx.x;
    float4 x = *(const float4*)&X[(size_t)row * 1024 + t * 4];
    float s = x.x + x.y + x.z + x.w;
    float q = fmaf(x.x, x.x, fmaf(x.y, x.y, fmaf(x.z, x.z, x.w * x.w)));
#pragma unroll
    for (int off = 16; off; off >>= 1) {
        s += __shfl_xor_sync(0xffffffffu, s, off);
        q += __shfl_xor_sync(0xffffffffu, q, off);
    }
    __shared__ float ss[8], qq[8];
    const int warp = t >> 5, lane = t & 31;
    if (lane == 0) { ss[warp] = s; qq[warp] = q; }
    __syncthreads();
    float S = 0.f, Q2 = 0.f;
#pragma unroll
    for (int i = 0; i < 8; ++i) { S += ss[i]; Q2 += qq[i]; }
    const float mean = S * (1.0f / 1024.0f);
    const float var  = fmaxf(Q2 * (1.0f / 1024.0f) - mean * mean, 0.f);
    const float inv  = rsqrtf(var + 1e-12f);
    float4 wv = *(const float4*)&w[t * 4];
    float4 bv = *(const float4*)&bb[t * 4];
    float4 y;
    y.x = wv.x * (x.x - mean) * inv + bv.x;
    y.y = wv.y * (x.y - mean) * inv + bv.y;
    y.z = wv.z * (x.z - mean) * inv + bv.z;
    y.w = wv.w * (x.w - mean) * inv + bv.w;
    *(float4*)&Y[(size_t)row * 1024 + t * 4] = y;
}

// ---------------- launch ----------------------------------------------------
static constexpr int TG_SMEM = 65536;   // 4 stages x 16KB

extern "C" void kernel_launch(void* const* d_in, const int* in_sizes, int n_in,
                              void* d_out, int out_size)
{
    const float* x     = (const float*)d_in[0];
    const float* in_w  = (const float*)d_in[1];
    const float* in_b  = (const float*)d_in[2];
    const float* out_w = (const float*)d_in[3];
    const float* out_b = (const float*)d_in[4];
    const float* fc1_w = (const float*)d_in[5];
    const float* fc1_b = (const float*)d_in[6];
    const float* fc2_w = (const float*)d_in[7];
    const float* fc2_b = (const float*)d_in[8];
    const float* ln1_w = (const float*)d_in[9];
    const float* ln1_b = (const float*)d_in[10];
    const float* ln2_w = (const float*)d_in[11];
    const float* ln2_b = (const float*)d_in[12];
    const void*  pad   = d_in[13];
    float* out = (float*)d_out;

    float *qkv, *attn, *sbuf, *x1, *ff;
    int* lenv;
    cudaGetSymbolAddress((void**)&qkv,  g_qkv);
    cudaGetSymbolAddress((void**)&attn, g_attn);
    cudaGetSymbolAddress((void**)&sbuf, g_s);
    cudaGetSymbolAddress((void**)&x1,   g_x1);
    cudaGetSymbolAddress((void**)&ff,   g_ff);
    cudaGetSymbolAddress((void**)&lenv, g_len);

    static bool attr_done = false;
    if (!attr_done) {
        cudaFuncSetAttribute(tgemm_kernel<0>, cudaFuncAttributeMaxDynamicSharedMemorySize, TG_SMEM);
        cudaFuncSetAttribute(tgemm_kernel<1>, cudaFuncAttributeMaxDynamicSharedMemorySize, TG_SMEM);
        cudaFuncSetAttribute(tgemm_kernel<2>, cudaFuncAttributeMaxDynamicSharedMemorySize, TG_SMEM);
        attr_done = true;
    }

    mask_len_kernel<<<1, 256>>>(pad);
    // 1) qkv = x @ in_w^T + in_b           [8192, 3072]
    tgemm_kernel<0><<<dim3(24, 64), 256, TG_SMEM>>>(x, in_w, in_b, nullptr, qkv, 1024, 3072);
    // 2) attention -> attn                 [8192, 1024]
    attn_kernel<<<dim3(16, 16, 8), 128>>>(qkv, lenv, attn);
    // 3) s1 = attn @ out_w^T + out_b + x   [8192, 1024]
    tgemm_kernel<1><<<dim3(8, 64), 256, TG_SMEM>>>(attn, out_w, out_b, x, sbuf, 1024, 1024);
    // 4) x1 = LN1(s1)
    ln_kernel<<<8192, 256>>>(sbuf, ln1_w, ln1_b, x1);
    // 5) ff = relu(x1 @ fc1_w^T + fc1_b)   [8192, 4096]
    tgemm_kernel<2><<<dim3(32, 64), 256, TG_SMEM>>>(x1, fc1_w, fc1_b, nullptr, ff, 1024, 4096);
    // 6) s2 = ff @ fc2_w^T + fc2_b + x1    [8192, 1024]
    tgemm_kernel<1><<<dim3(8, 64), 256, TG_SMEM>>>(ff, fc2_w, fc2_b, x1, sbuf, 4096, 1024);
    // 7) out = LN2(s2)
    ln_kernel<<<8192, 256>>>(sbuf, ln2_w, ln2_b, out);
}